// round 10
// baseline (speedup 1.0000x reference)
#include <cuda_runtime.h>

// GetCostVolume: out[b, c2, d, h, w], B=4 C=32 D=48 H=64 W=128
//   c2 <  32 : x[b, c2, h, w]        if w >= d else 0
//   c2 >= 32 : y[b, c2-32, h, w-d]   if w >= d else 0
//
// R9 (= R8 resubmit): R6 traffic shape (register x, zero-prefixed smem y,
// full 48-d loop, NO redundant staging) with 128-thread blocks / h-tile of 4:
// grid (16,128) = 2048 blocks -> 2x R6's schedulable units at zero extra
// work; launch_bounds(128,12) caps regs so 12 blocks (48 warps) fit per SM.

#define D_   48
#define SY_STRIDE 184    // > p(175)=180, p(i)=i+(i>>5)

__global__ __launch_bounds__(128, 12) void cost_volume_kernel(
    const float* __restrict__ x,
    const float* __restrict__ y,
    float* __restrict__ out)
{
    __shared__ float s_y[4][SY_STRIDE];

    int t  = threadIdx.x;
    int w4 = t & 31;
    int hs = t >> 5;                  // 0..3 (warp id = h sub-row)
    int ht = blockIdx.x;              // 0..15, h tile
    int bc = blockIdx.y;              // b*32 + c
    int h  = (ht << 2) + hs;          // 0..63

    int rowv = (bc * 64 + h) * 32;    // float4 offset of (b,c,h) row

    // Zero prefix slots [0,48) for the 4 rows (192 entries)
    for (int idx = t; idx < 4 * 48; idx += 128) {
        int r = idx / 48;
        int i = idx - r * 48;
        s_y[r][i + (i >> 5)] = 0.0f;
    }

    // Stage y row into padded slots 48+
    {
        float4 v = reinterpret_cast<const float4*>(y)[rowv + w4];
        int i = 48 + (w4 << 2);
        s_y[hs][(i + 0) + ((i + 0) >> 5)] = v.x;
        s_y[hs][(i + 1) + ((i + 1) >> 5)] = v.y;
        s_y[hs][(i + 2) + ((i + 2) >> 5)] = v.z;
        s_y[hs][(i + 3) + ((i + 3) >> 5)] = v.w;
    }

    // x float4 lives in registers for all 48 iterations
    float4 xv = reinterpret_cast<const float4*>(x)[rowv + w4];

    __syncthreads();

    int w0 = w4 << 2;
    int b  = bc >> 5;
    int c  = bc & 31;
    int hw = (h << 5) + w4;
    int basex = ((b * 64 + c) * D_) * 2048 + hw;  // float4 units, c2 = c
    int basey = basex + 32 * D_ * 2048;           // c2 = c + 32

    float4* outv = reinterpret_cast<float4*>(out);
    const float* yr = s_y[hs];

#pragma unroll 8
    for (int d = 0; d < D_; d++) {
        float4 vx;
        vx.x = (w0 + 0 >= d) ? xv.x : 0.0f;
        vx.y = (w0 + 1 >= d) ? xv.y : 0.0f;
        vx.z = (w0 + 2 >= d) ? xv.z : 0.0f;
        vx.w = (w0 + 3 >= d) ? xv.w : 0.0f;

        int i0 = 48 + w0 - d;                     // always >= 1
        float4 vy;
        vy.x = yr[(i0 + 0) + ((i0 + 0) >> 5)];
        vy.y = yr[(i0 + 1) + ((i0 + 1) >> 5)];
        vy.z = yr[(i0 + 2) + ((i0 + 2) >> 5)];
        vy.w = yr[(i0 + 3) + ((i0 + 3) >> 5)];

        int doff = d << 11;
        outv[basex + doff] = vx;
        outv[basey + doff] = vy;
    }
}

extern "C" void kernel_launch(void* const* d_in, const int* in_sizes, int n_in,
                              void* d_out, int out_size)
{
    const float* x = (const float*)d_in[0];
    const float* y = (const float*)d_in[1];
    float* out = (float*)d_out;

    dim3 grid(16, 128);   // (h tile of 4, b*32+c) = 2048 blocks, no redundancy
    cost_volume_kernel<<<grid, 128>>>(x, y, out);
}

// round 14
// speedup vs baseline: 1.2910x; 1.2910x over previous
#include <cuda_runtime.h>

// GetCostVolume: out[b, c2, d, h, w], B=4 C=32 D=48 H=64 W=128
//   c2 <  32 : x[b, c2, h, w]        if w >= d else 0
//   c2 >= 32 : y[b, c2-32, h, w-d]   if w >= d else 0
//
// R10: NO shared memory. The y-half is a register sliding window:
//   vy(d) = y[w0-d .. w0+3-d] (masked). Slide d->d+1:
//   vy' = (shfl_up(vy.w, 1) [0 for lane 0], vy.x, vy.y, vy.z)
// The zero-mask propagates automatically through the slide. 1 SHFL per
// iteration replaces 4 LDS -> L1tex wavefronts per warp-d drop 12 -> 8.
// Blocks split d (init window via 4 L2-hot scalar LDGs), no sync anywhere.
//
// Block 256 = (h 8 x w4 32); grid (8 h-tiles, 128 bc, 2 d-chunks of 24).

#define D_   48
#define DCH  24

__global__ __launch_bounds__(256) void cost_volume_kernel(
    const float* __restrict__ x,
    const float* __restrict__ y,
    float* __restrict__ out)
{
    int t  = threadIdx.x;
    int w4 = t & 31;                  // lane id == w4 (shfl neighbor = w4-1)
    int hs = t >> 5;
    int ht = blockIdx.x;              // 0..7
    int bc = blockIdx.y;              // b*32 + c
    int d0 = blockIdx.z * DCH;        // 0 or 24
    int h  = (ht << 3) + hs;

    int rowv = (bc * 64 + h) * 32;    // float4 offset of (b,c,h) row
    int w0 = w4 << 2;

    // x float4 (aligned vector load, L2-hot)
    float4 xv = reinterpret_cast<const float4*>(x)[rowv + w4];

    // init y sliding window at d = d0: vy.j = (w0+j >= d0) ? y[w0+j-d0] : 0
    const float* yb = y + (rowv << 2);
    float4 vy;
    vy.x = (w0 + 0 >= d0) ? yb[w0 + 0 - d0] : 0.0f;
    vy.y = (w0 + 1 >= d0) ? yb[w0 + 1 - d0] : 0.0f;
    vy.z = (w0 + 2 >= d0) ? yb[w0 + 2 - d0] : 0.0f;
    vy.w = (w0 + 3 >= d0) ? yb[w0 + 3 - d0] : 0.0f;

    int b  = bc >> 5;
    int c  = bc & 31;
    int hw = (h << 5) + w4;
    int basex = ((b * 64 + c) * D_) * 2048 + hw;  // float4 units, c2 = c
    int basey = basex + 32 * D_ * 2048;           // c2 = c + 32

    float4* outv = reinterpret_cast<float4*>(out);

#pragma unroll
    for (int k = 0; k < DCH; k++) {
        int d = d0 + k;

        float4 vx;
        vx.x = (w0 + 0 >= d) ? xv.x : 0.0f;
        vx.y = (w0 + 1 >= d) ? xv.y : 0.0f;
        vx.z = (w0 + 2 >= d) ? xv.z : 0.0f;
        vx.w = (w0 + 3 >= d) ? xv.w : 0.0f;

        int doff = (d << 11);
        outv[basex + doff] = vx;
        outv[basey + doff] = vy;

        // slide window: vy(d+1) = (y[w0-1-d] from lane-1, vy.x, vy.y, vy.z)
        float prev = __shfl_up_sync(0xffffffffu, vy.w, 1);
        vy.w = vy.z;
        vy.z = vy.y;
        vy.y = vy.x;
        vy.x = (w4 == 0) ? 0.0f : prev;
    }
}

extern "C" void kernel_launch(void* const* d_in, const int* in_sizes, int n_in,
                              void* d_out, int out_size)
{
    const float* x = (const float*)d_in[0];
    const float* y = (const float*)d_in[1];
    float* out = (float*)d_out;

    dim3 grid(8, 128, 2);   // (h tile of 8, b*32+c, d chunk of 24)
    cost_volume_kernel<<<grid, 256>>>(x, y, out);
}

// round 15
// speedup vs baseline: 1.3594x; 1.0530x over previous
#include <cuda_runtime.h>

// GetCostVolume: out[b, c2, d, h, w], B=4 C=32 D=48 H=64 W=128
//   c2 <  32 : x[b, c2, h, w]        if w >= d else 0
//   c2 >= 32 : y[b, c2-32, h, w-d]   if w >= d else 0
//
// R14 = R6 (best: fat 1024-block grid, 48-d loop, register x, zero-prefixed
// smem y) with the y-half turned into a PER-THREAD sliding window:
//   vy(d+1) = (s_y[47+w0-d], vy.x, vy.y, vy.z)
// -> 1 LDS per iteration instead of 4, no cross-lane dependency (unlike the
// R10 shfl chain), masking still free via the 48-float zero prefix.
// Padded smem p(i)=i+(i>>5): stride-4 lane reads conflict-free.

#define D_   48
#define SY_STRIDE 184    // > p(175)=180

#define P_(i) ((i) + ((i) >> 5))

__global__ __launch_bounds__(256) void cost_volume_kernel(
    const float* __restrict__ x,
    const float* __restrict__ y,
    float* __restrict__ out)
{
    __shared__ float s_y[8][SY_STRIDE];

    int t  = threadIdx.x;
    int w4 = t & 31;
    int hs = t >> 5;                  // 0..7 (warp id = h sub-row)
    int ht = blockIdx.x;              // 0..7, h tile
    int bc = blockIdx.y;              // b*32 + c
    int h  = (ht << 3) + hs;          // 0..63

    int rowv = (bc * 64 + h) * 32;    // float4 offset of (b,c,h) row

    // Zero prefix slots [0,48) for all 8 rows
    for (int idx = t; idx < 8 * 48; idx += 256) {
        int r = idx / 48, i = idx - r * 48;
        s_y[r][P_(i)] = 0.0f;
    }

    // Stage y row into padded slots 48+
    {
        float4 v = reinterpret_cast<const float4*>(y)[rowv + w4];
        int i = 48 + (w4 << 2);
        s_y[hs][P_(i + 0)] = v.x;
        s_y[hs][P_(i + 1)] = v.y;
        s_y[hs][P_(i + 2)] = v.z;
        s_y[hs][P_(i + 3)] = v.w;
    }

    // x float4 lives in registers for all 48 iterations
    float4 xv = reinterpret_cast<const float4*>(x)[rowv + w4];

    __syncthreads();

    int w0 = w4 << 2;
    int b  = bc >> 5;
    int c  = bc & 31;
    int hw = (h << 5) + w4;
    int basex = ((b * 64 + c) * D_) * 2048 + hw;  // float4 units, c2 = c
    int basey = basex + 32 * D_ * 2048;           // c2 = c + 32

    float4* outv = reinterpret_cast<float4*>(out);
    const float* yr = s_y[hs];

    // init window at d = 0: vy = y[w0 .. w0+3]
    float4 vy;
    vy.x = yr[P_(48 + w0 + 0)];
    vy.y = yr[P_(48 + w0 + 1)];
    vy.z = yr[P_(48 + w0 + 2)];
    vy.w = yr[P_(48 + w0 + 3)];

#pragma unroll
    for (int d = 0; d < D_; d++) {
        float4 vx;
        vx.x = (w0 + 0 >= d) ? xv.x : 0.0f;
        vx.y = (w0 + 1 >= d) ? xv.y : 0.0f;
        vx.z = (w0 + 2 >= d) ? xv.z : 0.0f;
        vx.w = (w0 + 3 >= d) ? xv.w : 0.0f;

        int doff = d << 11;
        outv[basex + doff] = vx;
        outv[basey + doff] = vy;

        // slide: next vy = (y[w0-1-d], vy.x, vy.y, vy.z); index 47+w0-d >= 0
        float nx = yr[P_(47 + w0 - d)];
        vy.w = vy.z;
        vy.z = vy.y;
        vy.y = vy.x;
        vy.x = nx;
    }
}

extern "C" void kernel_launch(void* const* d_in, const int* in_sizes, int n_in,
                              void* d_out, int out_size)
{
    const float* x = (const float*)d_in[0];
    const float* y = (const float*)d_in[1];
    float* out = (float*)d_out;

    dim3 grid(8, 128);   // (h tile of 8, b*32+c) = 1024 fat blocks (R6 schedule)
    cost_volume_kernel<<<grid, 256>>>(x, y, out);
}

// round 17
// speedup vs baseline: 1.4521x; 1.0682x over previous
#include <cuda_runtime.h>

// GetCostVolume: out[b, c2, d, h, w], B=4 C=32 D=48 H=64 W=128
//   c2 <  32 : x[b, c2, h, w]        if w >= d else 0
//   c2 >= 32 : y[b, c2-32, h, w-d]   if w >= d else 0
//
// R15 = R14 (fat 1024-block grid, register x, zero-prefixed smem y with
// per-thread sliding window: 1 LDS per d) + EVICT-FIRST streaming stores
// (__stcs -> STG.E.128.CS). Output is write-once-never-read: evict-first
// stops 402 MB of store lines from churning L2 at normal priority and lets
// LTS drain write sectors to DRAM sooner. Bytes written are irreducible;
// this targets write-path efficiency only.

#define D_   48
#define SY_STRIDE 184    // > p(175)=180
#define P_(i) ((i) + ((i) >> 5))

__global__ __launch_bounds__(256) void cost_volume_kernel(
    const float* __restrict__ x,
    const float* __restrict__ y,
    float* __restrict__ out)
{
    __shared__ float s_y[8][SY_STRIDE];

    int t  = threadIdx.x;
    int w4 = t & 31;
    int hs = t >> 5;                  // 0..7 (warp id = h sub-row)
    int ht = blockIdx.x;              // 0..7, h tile
    int bc = blockIdx.y;              // b*32 + c
    int h  = (ht << 3) + hs;          // 0..63

    int rowv = (bc * 64 + h) * 32;    // float4 offset of (b,c,h) row

    // Zero prefix slots [0,48) for all 8 rows
    for (int idx = t; idx < 8 * 48; idx += 256) {
        int r = idx / 48, i = idx - r * 48;
        s_y[r][P_(i)] = 0.0f;
    }

    // Stage y row into padded slots 48+
    {
        float4 v = reinterpret_cast<const float4*>(y)[rowv + w4];
        int i = 48 + (w4 << 2);
        s_y[hs][P_(i + 0)] = v.x;
        s_y[hs][P_(i + 1)] = v.y;
        s_y[hs][P_(i + 2)] = v.z;
        s_y[hs][P_(i + 3)] = v.w;
    }

    // x float4 lives in registers for all 48 iterations
    float4 xv = reinterpret_cast<const float4*>(x)[rowv + w4];

    __syncthreads();

    int w0 = w4 << 2;
    int b  = bc >> 5;
    int c  = bc & 31;
    int hw = (h << 5) + w4;
    int basex = ((b * 64 + c) * D_) * 2048 + hw;  // float4 units, c2 = c
    int basey = basex + 32 * D_ * 2048;           // c2 = c + 32

    float4* outv = reinterpret_cast<float4*>(out);
    const float* yr = s_y[hs];

    // init window at d = 0: vy = y[w0 .. w0+3]
    float4 vy;
    vy.x = yr[P_(48 + w0 + 0)];
    vy.y = yr[P_(48 + w0 + 1)];
    vy.z = yr[P_(48 + w0 + 2)];
    vy.w = yr[P_(48 + w0 + 3)];

#pragma unroll
    for (int d = 0; d < D_; d++) {
        float4 vx;
        vx.x = (w0 + 0 >= d) ? xv.x : 0.0f;
        vx.y = (w0 + 1 >= d) ? xv.y : 0.0f;
        vx.z = (w0 + 2 >= d) ? xv.z : 0.0f;
        vx.w = (w0 + 3 >= d) ? xv.w : 0.0f;

        int doff = d << 11;
        __stcs(&outv[basex + doff], vx);   // streaming, evict-first
        __stcs(&outv[basey + doff], vy);

        // slide: next vy = (y[w0-1-d], vy.x, vy.y, vy.z); index 47+w0-d >= 0
        float nx = yr[P_(47 + w0 - d)];
        vy.w = vy.z;
        vy.z = vy.y;
        vy.y = vy.x;
        vy.x = nx;
    }
}

extern "C" void kernel_launch(void* const* d_in, const int* in_sizes, int n_in,
                              void* d_out, int out_size)
{
    const float* x = (const float*)d_in[0];
    const float* y = (const float*)d_in[1];
    float* out = (float*)d_out;

    dim3 grid(8, 128);   // (h tile of 8, b*32+c) = 1024 fat blocks
    cost_volume_kernel<<<grid, 256>>>(x, y, out);
}